// round 10
// baseline (speedup 1.0000x reference)
#include <cuda_runtime.h>
#include <cuda_fp16.h>
#include <cstdint>

#define MDIM 16384
#define NDIM 1024
#define KDIM 4096

#define BM 128
#define BN 128
#define BK 32
#define KT (KDIM / BK)             // 128 k-tiles
#define NTILES ((MDIM / BM) * (NDIM / BN))   // 1024 tiles
#define GEMM_GRID 296              // 148 SMs x 2 persistent CTAs
#define ROWB 80                    // 32 halves (64 B) + 16 pad; 16B-aligned rows for ldmatrix
#define TILE_BYTES (BM * ROWB)     // 10240 per (A16 or B) tile
#define B_OFF 0                    // 3 B stages
#define A16_OFF (3 * TILE_BYTES)   // 2 A fp16 buffers
#define CTR_OFF (5 * TILE_BYTES)   // tile-id broadcast slot
#define SMEM_BYTES (5 * TILE_BYTES + 16)   // 51216 (x2 CTAs = 100 KB)

// ---------------- device scratch ----------------
__device__ __align__(16) uint16_t g_w[(size_t)NDIM * KDIM];   // fp16 w_int (8 MB)
__device__ float g_scale[NDIM];
__device__ unsigned g_tile_ctr;

// ---------------- PTX helpers ----------------
__device__ __forceinline__ uint32_t smem_u32(const void* p) {
    uint32_t a;
    asm("{ .reg .u64 t; cvta.to.shared.u64 t, %1; cvt.u32.u64 %0, t; }" : "=r"(a) : "l"(p));
    return a;
}
__device__ __forceinline__ void cp16(uint32_t dst, const void* src) {
    asm volatile("cp.async.cg.shared.global [%0], [%1], 16;" :: "r"(dst), "l"(src));
}
__device__ __forceinline__ void cp_commit() {
    asm volatile("cp.async.commit_group;" ::: "memory");
}
template <int N> __device__ __forceinline__ void cp_wait() {
    asm volatile("cp.async.wait_group %0;" :: "n"(N) : "memory");
}
__device__ __forceinline__ void ldsm4(uint32_t& r0, uint32_t& r1, uint32_t& r2, uint32_t& r3,
                                      uint32_t addr) {
    asm volatile("ldmatrix.sync.aligned.m8n8.x4.shared.b16 {%0,%1,%2,%3}, [%4];"
                 : "=r"(r0), "=r"(r1), "=r"(r2), "=r"(r3) : "r"(addr));
}
__device__ __forceinline__ void mma16816(float& d0, float& d1, float& d2, float& d3,
                                         uint32_t a0, uint32_t a1, uint32_t a2, uint32_t a3,
                                         uint32_t b0, uint32_t b1) {
    asm volatile(
        "mma.sync.aligned.m16n8k16.row.col.f32.f16.f16.f32 "
        "{%0,%1,%2,%3}, {%4,%5,%6,%7}, {%8,%9}, {%0,%1,%2,%3};"
        : "+f"(d0), "+f"(d1), "+f"(d2), "+f"(d3)
        : "r"(a0), "r"(a1), "r"(a2), "r"(a3), "r"(b0), "r"(b1));
}

// ---------------- kernel 1: W fake-quant (vectorized) ----------------
__global__ void prep_kernel(const float* __restrict__ W) {
    int tid = threadIdx.x;
    int d = blockIdx.x;
    if (d == 0 && tid == 0) g_tile_ctr = 0;   // reset persistent-GEMM counter

    const float4* row4 = reinterpret_cast<const float4*>(W + (size_t)d * KDIM);
    float4 f[4];
    float m = 0.f;
    #pragma unroll
    for (int i = 0; i < 4; i++) {
        f[i] = row4[i * 256 + tid];
        m = fmaxf(m, fmaxf(fmaxf(fabsf(f[i].x), fabsf(f[i].y)),
                           fmaxf(fabsf(f[i].z), fabsf(f[i].w))));
    }
    #pragma unroll
    for (int o = 16; o; o >>= 1) m = fmaxf(m, __shfl_xor_sync(0xffffffffu, m, o));

    __shared__ float red[8];
    if ((tid & 31) == 0) red[tid >> 5] = m;
    __syncthreads();
    if (tid < 8) {
        float v = red[tid];
        #pragma unroll
        for (int o = 4; o; o >>= 1) v = fmaxf(v, __shfl_xor_sync(0xffu, v, o));
        if (tid == 0) red[0] = v;
    }
    __syncthreads();

    float scale = fmaxf(red[0], 1e-8f) / 127.f;
    if (tid == 0) g_scale[d] = scale;

    uint2* wout = reinterpret_cast<uint2*>(g_w + (size_t)d * KDIM);
    #pragma unroll
    for (int i = 0; i < 4; i++) {
        float qx = fminf(fmaxf(rintf(f[i].x / scale), -128.f), 127.f);
        float qy = fminf(fmaxf(rintf(f[i].y / scale), -128.f), 127.f);
        float qz = fminf(fmaxf(rintf(f[i].z / scale), -128.f), 127.f);
        float qw = fminf(fmaxf(rintf(f[i].w / scale), -128.f), 127.f);
        __half2 lo = __floats2half2_rn(qx, qy);        // exact ints in fp16
        __half2 hi = __floats2half2_rn(qz, qw);
        uint2 o;
        o.x = *reinterpret_cast<uint32_t*>(&lo);
        o.y = *reinterpret_cast<uint32_t*>(&hi);
        wout[i * 256 + tid] = o;
    }
}

// ---------------- kernel 2: persistent GEMM with fused fp32->fp16 A conversion ----------------
__device__ __forceinline__ void ldg_a(float4 f[4], const float* __restrict__ H,
                                      int m0, int t, int row, int q) {
    const float4* p = reinterpret_cast<const float4*>(
        H + (size_t)(m0 + row) * KDIM + t * BK + q * 16);
    f[0] = p[0]; f[1] = p[1]; f[2] = p[2]; f[3] = p[3];
}
__device__ __forceinline__ void cvt_sts_a(char* smem, uint32_t a16_off, const float4 f[4],
                                          int row, int q) {
    uint4* dst = reinterpret_cast<uint4*>(smem + a16_off + row * ROWB + q * 32);
    #pragma unroll
    for (int j = 0; j < 2; j++) {
        __half2 h0 = __floats2half2_rn(f[2 * j].x, f[2 * j].y);
        __half2 h1 = __floats2half2_rn(f[2 * j].z, f[2 * j].w);
        __half2 h2 = __floats2half2_rn(f[2 * j + 1].x, f[2 * j + 1].y);
        __half2 h3 = __floats2half2_rn(f[2 * j + 1].z, f[2 * j + 1].w);
        uint4 v;
        v.x = *reinterpret_cast<uint32_t*>(&h0);
        v.y = *reinterpret_cast<uint32_t*>(&h1);
        v.z = *reinterpret_cast<uint32_t*>(&h2);
        v.w = *reinterpret_cast<uint32_t*>(&h3);
        dst[j] = v;
    }
}
__device__ __forceinline__ void ldgsts_b(uint32_t sb, int s, int tid, int n0, int t) {
    uint32_t base = sb + B_OFF + (uint32_t)s * TILE_BYTES;
    int k0 = t * BK;
    #pragma unroll
    for (int i = 0; i < 2; i++) {                 // 512 16B-chunks over 256 threads
        int cid = i * 256 + tid;
        int row = cid >> 2, col = cid & 3;
        cp16(base + (uint32_t)(row * ROWB + col * 16),
             reinterpret_cast<const __half*>(g_w) + (size_t)(n0 + row) * KDIM + k0 + col * 8);
    }
}

__global__ void __launch_bounds__(256, 2) gemm_kernel(const float* __restrict__ H,
                                                      const float* __restrict__ bias,
                                                      const float* __restrict__ input,
                                                      float* __restrict__ out) {
    extern __shared__ char smem[];
    uint32_t sb = smem_u32(smem);
    int tid = threadIdx.x;
    int wid = tid >> 5, lane = tid & 31;
    int g = lane >> 2, c = lane & 3;
    int wm = wid & 1, wn = wid >> 1;              // 2 x 4 warp grid, warp tile 64x32
    int arow = tid >> 1, aq = tid & 1;            // per-thread A-load coords

    unsigned* s_tile = reinterpret_cast<unsigned*>(smem + CTR_OFF);

    uint32_t a_loff = (uint32_t)((wm * 64 + (lane & 15)) * ROWB + (lane >> 4) * 16);
    uint32_t b_loff = (uint32_t)(B_OFF +
                      (wn * 32 + (lane >> 4) * 8 + (lane & 7)) * ROWB +
                      (((lane >> 3) & 1) * 16));

    while (true) {
        if (tid == 0) *s_tile = atomicAdd(&g_tile_ctr, 1u);
        __syncthreads();                          // broadcast; prior tile fully done
        unsigned tile = *s_tile;
        if (tile >= NTILES) break;

        int m0 = (int)(tile >> 3) * BM;           // m-major, n-inner: A m-block L2-shared
        int n0 = (int)(tile & 7) * BN;

        // prologue
        float4 af[4];
        ldg_a(af, H, m0, 0, arow, aq);
        ldgsts_b(sb, 0, tid, n0, 0); cp_commit();
        ldgsts_b(sb, 1, tid, n0, 1); cp_commit();
        cvt_sts_a(smem, A16_OFF, af, arow, aq);   // A16[0]

        float acc[4][4][4];
        #pragma unroll
        for (int mt = 0; mt < 4; mt++)
            #pragma unroll
            for (int nt = 0; nt < 4; nt++)
                #pragma unroll
                for (int r = 0; r < 4; r++) acc[mt][nt][r] = 0.f;

        for (int t = 0; t < KT; t++) {
            cp_wait<1>();                         // B(t) resident
            __syncthreads();                      // + A16[t&1] STS visible CTA-wide

            if (t + 2 < KT) ldgsts_b(sb, (t + 2) % 3, tid, n0, t + 2);
            cp_commit();
            if (t + 1 < KT) ldg_a(af, H, m0, t + 1, arow, aq);

            uint32_t stageA = sb + A16_OFF + (uint32_t)((t & 1) * TILE_BYTES);
            uint32_t stageB = sb + (uint32_t)((t % 3) * TILE_BYTES);
            #pragma unroll
            for (int ks = 0; ks < 2; ks++) {
                uint32_t a[4][4], b[2][4];
                #pragma unroll
                for (int mt = 0; mt < 4; mt++)
                    ldsm4(a[mt][0], a[mt][1], a[mt][2], a[mt][3],
                          stageA + a_loff + (uint32_t)(mt * 16 * ROWB) + (uint32_t)(ks * 32));
                #pragma unroll
                for (int p = 0; p < 2; p++)
                    ldsm4(b[p][0], b[p][1], b[p][2], b[p][3],
                          stageB + b_loff + (uint32_t)(p * 16 * ROWB) + (uint32_t)(ks * 32));
                #pragma unroll
                for (int mt = 0; mt < 4; mt++)
                    #pragma unroll
                    for (int nt = 0; nt < 4; nt++) {
                        int p = nt >> 1, q = nt & 1;
                        mma16816(acc[mt][nt][0], acc[mt][nt][1], acc[mt][nt][2], acc[mt][nt][3],
                                 a[mt][0], a[mt][1], a[mt][2], a[mt][3],
                                 b[p][2 * q], b[p][2 * q + 1]);
                    }
            }

            if (t + 1 < KT)                       // convert next A into the other buffer
                cvt_sts_a(smem, A16_OFF + (uint32_t)(((t + 1) & 1) * TILE_BYTES), af, arow, aq);
        }

        // epilogue: out = acc * scale[n] + bias[n] + input  (scale/bias L2-hot)
        #pragma unroll
        for (int nt = 0; nt < 4; nt++) {
            int n = n0 + wn * 32 + nt * 8 + 2 * c;
            float sc0 = g_scale[n], sc1 = g_scale[n + 1];
            float bi0 = bias[n],    bi1 = bias[n + 1];
            #pragma unroll
            for (int mt = 0; mt < 4; mt++) {
                int mA = m0 + wm * 64 + mt * 16 + g;
                int mB = mA + 8;
                const float2* inA = reinterpret_cast<const float2*>(input + (size_t)mA * NDIM + n);
                const float2* inB = reinterpret_cast<const float2*>(input + (size_t)mB * NDIM + n);
                float2* outA = reinterpret_cast<float2*>(out + (size_t)mA * NDIM + n);
                float2* outB = reinterpret_cast<float2*>(out + (size_t)mB * NDIM + n);

                float2 ia = *inA, ib = *inB, oa, ob;
                oa.x = acc[mt][nt][0] * sc0 + bi0 + ia.x;
                oa.y = acc[mt][nt][1] * sc1 + bi1 + ia.y;
                ob.x = acc[mt][nt][2] * sc0 + bi0 + ib.x;
                ob.y = acc[mt][nt][3] * sc1 + bi1 + ib.y;
                *outA = oa;
                *outB = ob;
            }
        }
    }
}

// ---------------- launch ----------------
extern "C" void kernel_launch(void* const* d_in, const int* in_sizes, int n_in,
                              void* d_out, int out_size) {
    const float* hidden = (const float*)d_in[0];   // [16,1024,4096]
    const float* input  = (const float*)d_in[1];   // [16,1024,1024]
    const float* W      = (const float*)d_in[2];   // [1024,4096]
    const float* b      = (const float*)d_in[3];   // [1024]
    float* out = (float*)d_out;

    prep_kernel<<<NDIM, 256>>>(W);

    cudaFuncSetAttribute(gemm_kernel, cudaFuncAttributeMaxDynamicSharedMemorySize, SMEM_BYTES);
    gemm_kernel<<<GEMM_GRID, 256, SMEM_BYTES>>>(hidden, b, input, out);
}

// round 11
// speedup vs baseline: 1.3435x; 1.3435x over previous
#include <cuda_runtime.h>
#include <cuda_fp16.h>
#include <cstdint>

#define MDIM 16384
#define NDIM 1024
#define KDIM 4096

#define BM 128
#define BN 128
#define BK 64
#define NSTAGE 3
#define KT (KDIM / BK)              // 64 k-tiles
#define TC (KT / 4)                 // 16 chunks of 4 k-tiles (K=256 per f16 chain)
#define SSTRIDE 72                  // halves per smem row (64 + 8 pad) -> 144 B
#define ROWB (SSTRIDE * 2)          // 144 bytes per row
#define A_STAGE_B (BM * ROWB)       // 18432
#define STAGE_B   (2 * A_STAGE_B)   // 36864 (A then B)
#define SMEM_BYTES (1024 + NSTAGE * STAGE_B)  // 111616 (x2 CTAs fits 228KB)

// ---------------- device scratch ----------------
__device__ __align__(16) uint16_t g_h[(size_t)MDIM * KDIM];   // fp16 hidden (128 MB)
__device__ __align__(16) uint16_t g_w[(size_t)NDIM * KDIM];   // fp16 w_int  (8 MB)
__device__ float g_scale[NDIM];

// ---------------- PTX helpers ----------------
__device__ __forceinline__ uint32_t smem_u32(const void* p) {
    uint32_t a;
    asm("{ .reg .u64 t; cvta.to.shared.u64 t, %1; cvt.u32.u64 %0, t; }" : "=r"(a) : "l"(p));
    return a;
}
__device__ __forceinline__ void cp16(uint32_t dst, const void* src) {
    asm volatile("cp.async.cg.shared.global [%0], [%1], 16;" :: "r"(dst), "l"(src));
}
__device__ __forceinline__ void cp_commit() {
    asm volatile("cp.async.commit_group;" ::: "memory");
}
template <int N> __device__ __forceinline__ void cp_wait() {
    asm volatile("cp.async.wait_group %0;" :: "n"(N) : "memory");
}
__device__ __forceinline__ void ldsm4(uint32_t& r0, uint32_t& r1, uint32_t& r2, uint32_t& r3,
                                      uint32_t addr) {
    asm volatile("ldmatrix.sync.aligned.m8n8.x4.shared.b16 {%0,%1,%2,%3}, [%4];"
                 : "=r"(r0), "=r"(r1), "=r"(r2), "=r"(r3) : "r"(addr));
}
// fp16-accumulator MMA: d, c are 2 b32 regs (4 halves)
__device__ __forceinline__ void mma16816h(uint32_t& d0, uint32_t& d1,
                                          uint32_t a0, uint32_t a1, uint32_t a2, uint32_t a3,
                                          uint32_t b0, uint32_t b1,
                                          uint32_t c0, uint32_t c1) {
    asm volatile(
        "mma.sync.aligned.m16n8k16.row.col.f16.f16.f16.f16 "
        "{%0,%1}, {%2,%3,%4,%5}, {%6,%7}, {%8,%9};"
        : "=r"(d0), "=r"(d1)
        : "r"(a0), "r"(a1), "r"(a2), "r"(a3), "r"(b0), "r"(b1), "r"(c0), "r"(c1));
}

// ---------------- kernel 1: fused W fake-quant + H fp32->fp16 convert ----------------
__global__ void prep_kernel(const float* __restrict__ W, const float* __restrict__ H) {
    int tid = threadIdx.x;
    if (blockIdx.x < NDIM) {
        int d = blockIdx.x;
        const float4* row4 = reinterpret_cast<const float4*>(W + (size_t)d * KDIM);
        float4 f[4];
        float m = 0.f;
        #pragma unroll
        for (int i = 0; i < 4; i++) {
            f[i] = row4[i * 256 + tid];
            m = fmaxf(m, fmaxf(fmaxf(fabsf(f[i].x), fabsf(f[i].y)),
                               fmaxf(fabsf(f[i].z), fabsf(f[i].w))));
        }
        #pragma unroll
        for (int o = 16; o; o >>= 1) m = fmaxf(m, __shfl_xor_sync(0xffffffffu, m, o));

        __shared__ float red[8];
        if ((tid & 31) == 0) red[tid >> 5] = m;
        __syncthreads();
        if (tid < 8) {
            float v = red[tid];
            #pragma unroll
            for (int o = 4; o; o >>= 1) v = fmaxf(v, __shfl_xor_sync(0xffu, v, o));
            if (tid == 0) red[0] = v;
        }
        __syncthreads();

        float scale = fmaxf(red[0], 1e-8f) / 127.f;
        if (tid == 0) g_scale[d] = scale;

        uint2* wout = reinterpret_cast<uint2*>(g_w + (size_t)d * KDIM);
        #pragma unroll
        for (int i = 0; i < 4; i++) {
            float qx = fminf(fmaxf(rintf(f[i].x / scale), -128.f), 127.f);
            float qy = fminf(fmaxf(rintf(f[i].y / scale), -128.f), 127.f);
            float qz = fminf(fmaxf(rintf(f[i].z / scale), -128.f), 127.f);
            float qw = fminf(fmaxf(rintf(f[i].w / scale), -128.f), 127.f);
            __half2 lo = __floats2half2_rn(qx, qy);    // exact ints in fp16
            __half2 hi = __floats2half2_rn(qz, qw);
            uint2 o;
            o.x = *reinterpret_cast<uint32_t*>(&lo);
            o.y = *reinterpret_cast<uint32_t*>(&hi);
            wout[i * 256 + tid] = o;
        }
    } else {
        size_t i = (size_t)(blockIdx.x - NDIM) * 256 + tid;   // float4 index
        float4 v = reinterpret_cast<const float4*>(H)[i];
        __half2* outp = reinterpret_cast<__half2*>(g_h);
        outp[2 * i]     = __floats2half2_rn(v.x, v.y);
        outp[2 * i + 1] = __floats2half2_rn(v.z, v.w);
    }
}

// ---------------- kernel 2: fp16-accum mma GEMM (chunked), CTA 128x128 ----------------
__device__ __forceinline__ void load_stage(uint32_t stage_base, int tid, int m0, int n0, int t) {
    int k0 = t * BK;
    const __half* Ab = reinterpret_cast<const __half*>(g_h) + (size_t)m0 * KDIM + k0;
    #pragma unroll
    for (int i = 0; i < 4; i++) {
        int cid = i * 256 + tid;          // 1024 chunks of 16B
        int row = cid >> 3, col = cid & 7;
        cp16(stage_base + row * ROWB + col * 16, Ab + (size_t)row * KDIM + col * 8);
    }
    const __half* Bb = reinterpret_cast<const __half*>(g_w) + (size_t)n0 * KDIM + k0;
    uint32_t bbase = stage_base + A_STAGE_B;
    #pragma unroll
    for (int i = 0; i < 4; i++) {
        int cid = i * 256 + tid;
        int row = cid >> 3, col = cid & 7;
        cp16(bbase + row * ROWB + col * 16, Bb + (size_t)row * KDIM + col * 8);
    }
}

__global__ void __launch_bounds__(256, 2) gemm_kernel(const float* __restrict__ bias,
                                                      const float* __restrict__ input,
                                                      float* __restrict__ out) {
    extern __shared__ char smem[];
    uint32_t sb = smem_u32(smem);
    int tid = threadIdx.x;
    int wid = tid >> 5, lane = tid & 31;
    int g = lane >> 2, c = lane & 3;
    int wm = wid & 1, wn = wid >> 1;      // 2 x 4 warp grid, warp tile 64x32

    int mtile = blockIdx.x >> 3;          // 128 m-tiles
    int ntile = blockIdx.x & 7;           // 8 n-tiles (adjacent bids share A in L2)
    int m0 = mtile * BM, n0 = ntile * BN;

    float* s_scale = reinterpret_cast<float*>(smem);
    float* s_bias  = reinterpret_cast<float*>(smem + 512);
    if (tid < 128) {
        s_scale[tid] = g_scale[n0 + tid];
        s_bias[tid]  = bias[n0 + tid];
    }

    uint32_t a_loff = (uint32_t)((wm * 64 + (lane & 15)) * ROWB + (lane >> 4) * 16);
    uint32_t b_loff = (uint32_t)(A_STAGE_B +
                      (wn * 32 + (lane >> 4) * 8 + (lane & 7)) * ROWB +
                      (((lane >> 3) & 1) * 16));

    // prologue
    #pragma unroll
    for (int s = 0; s < NSTAGE; s++) {
        load_stage(sb + 1024u + (uint32_t)s * STAGE_B, tid, m0, n0, s);
        cp_commit();
    }

    float acc[4][4][4];                   // fp32 master accumulators
    #pragma unroll
    for (int mt = 0; mt < 4; mt++)
        #pragma unroll
        for (int nt = 0; nt < 4; nt++)
            #pragma unroll
            for (int r = 0; r < 4; r++) acc[mt][nt][r] = 0.f;

    uint32_t acch[4][4][2];               // fp16 chunk accumulators (4 halves each)

    for (int tc = 0; tc < TC; tc++) {
        #pragma unroll
        for (int ti = 0; ti < 4; ti++) {  // 4 k-tiles per chunk; ti compile-time
            int t = tc * 4 + ti;
            uint32_t stage = sb + 1024u + (uint32_t)(t % NSTAGE) * STAGE_B;

            cp_wait<NSTAGE - 1>();
            __syncthreads();

            #pragma unroll
            for (int ks = 0; ks < 4; ks++) {
                uint32_t b[2][4];
                #pragma unroll
                for (int p = 0; p < 2; p++)
                    ldsm4(b[p][0], b[p][1], b[p][2], b[p][3],
                          stage + b_loff + (uint32_t)(p * 16 * ROWB) + (uint32_t)(ks * 32));
                #pragma unroll
                for (int mt = 0; mt < 4; mt++) {
                    uint32_t a0, a1, a2, a3;
                    ldsm4(a0, a1, a2, a3,
                          stage + a_loff + (uint32_t)(mt * 16 * ROWB) + (uint32_t)(ks * 32));
                    #pragma unroll
                    for (int nt = 0; nt < 4; nt++) {
                        int p = nt >> 1, q = nt & 1;
                        if (ti == 0 && ks == 0)   // chunk start: c = 0
                            mma16816h(acch[mt][nt][0], acch[mt][nt][1],
                                      a0, a1, a2, a3, b[p][2 * q], b[p][2 * q + 1], 0u, 0u);
                        else
                            mma16816h(acch[mt][nt][0], acch[mt][nt][1],
                                      a0, a1, a2, a3, b[p][2 * q], b[p][2 * q + 1],
                                      acch[mt][nt][0], acch[mt][nt][1]);
                    }
                }
            }

            __syncthreads();              // all warps done reading stage t
            if (t + NSTAGE < KT)
                load_stage(stage, tid, m0, n0, t + NSTAGE);
            cp_commit();                  // empty group in tail keeps accounting exact
        }

        // chunk end: fold fp16 partials into fp32 accumulators
        #pragma unroll
        for (int mt = 0; mt < 4; mt++)
            #pragma unroll
            for (int nt = 0; nt < 4; nt++) {
                float2 lo = __half22float2(*reinterpret_cast<__half2*>(&acch[mt][nt][0]));
                float2 hi = __half22float2(*reinterpret_cast<__half2*>(&acch[mt][nt][1]));
                acc[mt][nt][0] += lo.x;
                acc[mt][nt][1] += lo.y;
                acc[mt][nt][2] += hi.x;
                acc[mt][nt][3] += hi.y;
            }
    }

    // epilogue: out = acc * scale[n] + bias[n] + input
    #pragma unroll
    for (int mt = 0; mt < 4; mt++) {
        #pragma unroll
        for (int nt = 0; nt < 4; nt++) {
            int nl = wn * 32 + nt * 8 + 2 * c;
            int n  = n0 + nl;
            float sc0 = s_scale[nl],     sc1 = s_scale[nl + 1];
            float bi0 = s_bias[nl],      bi1 = s_bias[nl + 1];
            int mA = m0 + wm * 64 + mt * 16 + g;
            int mB = mA + 8;

            const float2* inA = reinterpret_cast<const float2*>(input + (size_t)mA * NDIM + n);
            const float2* inB = reinterpret_cast<const float2*>(input + (size_t)mB * NDIM + n);
            float2* outA = reinterpret_cast<float2*>(out + (size_t)mA * NDIM + n);
            float2* outB = reinterpret_cast<float2*>(out + (size_t)mB * NDIM + n);

            float2 ia = *inA, ib = *inB, oa, ob;
            oa.x = acc[mt][nt][0] * sc0 + bi0 + ia.x;
            oa.y = acc[mt][nt][1] * sc1 + bi1 + ia.y;
            ob.x = acc[mt][nt][2] * sc0 + bi0 + ib.x;
            ob.y = acc[mt][nt][3] * sc1 + bi1 + ib.y;
            *outA = oa;
            *outB = ob;
        }
    }
}

// ---------------- launch ----------------
extern "C" void kernel_launch(void* const* d_in, const int* in_sizes, int n_in,
                              void* d_out, int out_size) {
    const float* hidden = (const float*)d_in[0];   // [16,1024,4096]
    const float* input  = (const float*)d_in[1];   // [16,1024,1024]
    const float* W      = (const float*)d_in[2];   // [1024,4096]
    const float* b      = (const float*)d_in[3];   // [1024]
    float* out = (float*)d_out;

    prep_kernel<<<NDIM + (int)((size_t)MDIM * KDIM / 4 / 256), 256>>>(W, hidden);

    cudaFuncSetAttribute(gemm_kernel, cudaFuncAttributeMaxDynamicSharedMemorySize, SMEM_BYTES);
    gemm_kernel<<<(MDIM / BM) * (NDIM / BN), 256, SMEM_BYTES>>>(b, input, out);
}